// round 8
// baseline (speedup 1.0000x reference)
#include <cuda_runtime.h>

#define N_NODES 100000
#define DIN     128
#define HDIM    64

// Scratch (device globals; zeroed at module load; k_out re-zeroes g_deg/g_acc2)
__device__ float  g_deg[N_NODES];     // edge-only degree (self-loop +1 at use)
__device__ float  g_s[N_NODES];       // raw dot product x.w
__device__ float  g_p1[N_NODES];      // dis * s (layer-1 gather array)
__device__ float2 g_H[N_NODES];       // {dis, acc1}; acc1 init = dis*s (self-loop)
__device__ float  g_acc2[N_NODES];    // layer-2 edge accumulator (zeroed)
__device__ float  g_c1;
__device__ float  g_c2;

__device__ __forceinline__ int4   ldcs4i(const int* p)   { return __ldcs((const int4*)p); }
__device__ __forceinline__ float4 ldcs4f(const float* p) { return __ldcs((const float4*)p); }

// ---------------------------------------------------------------------------
// K1 (fused):
//   blocks [0, nodeBlocks):           s[i] = x[i].w  (4 nodes/warp; per-block
//                                     weight collapse W2@fc_w -> u, W1@u -> w)
//   blocks [nodeBlocks, +edgeBlocks): deg[dst] += ew (4 edges/thread)
// ---------------------------------------------------------------------------
__global__ void k_fused(const float* __restrict__ x, int n, int nodeBlocks,
                        const int* __restrict__ dst, const float* __restrict__ ew, int E,
                        const float* __restrict__ W1, const float* __restrict__ W2,
                        const float* __restrict__ fc_w) {
    if ((int)blockIdx.x < nodeBlocks) {
        __shared__ float su[HDIM];
        __shared__ __align__(16) float sw[DIN];
        int t = threadIdx.x;
        if (t < HDIM) {
            float a = 0.f;
            #pragma unroll 8
            for (int j = 0; j < HDIM; ++j) a += W2[t * HDIM + j] * fc_w[j];
            su[t] = a;
        }
        __syncthreads();
        if (t < DIN) {
            float a = 0.f;
            #pragma unroll 8
            for (int j = 0; j < HDIM; ++j) a += W1[t * HDIM + j] * su[j];
            sw[t] = a;
        }
        __syncthreads();

        int warp = blockIdx.x * (blockDim.x >> 5) + (t >> 5);
        int lane = t & 31;
        int base = warp * 4;
        if (base >= n) return;

        float4 wv = ((const float4*)sw)[lane];
        float acc[4];
        if (base + 3 < n) {
            const float4* xr = (const float4*)(x + (size_t)base * DIN);
            float4 v0 = xr[lane];
            float4 v1 = xr[32 + lane];
            float4 v2 = xr[64 + lane];
            float4 v3 = xr[96 + lane];
            acc[0] = v0.x * wv.x + v0.y * wv.y + v0.z * wv.z + v0.w * wv.w;
            acc[1] = v1.x * wv.x + v1.y * wv.y + v1.z * wv.z + v1.w * wv.w;
            acc[2] = v2.x * wv.x + v2.y * wv.y + v2.z * wv.z + v2.w * wv.w;
            acc[3] = v3.x * wv.x + v3.y * wv.y + v3.z * wv.z + v3.w * wv.w;
        } else {
            #pragma unroll
            for (int k = 0; k < 4; ++k) {
                if (base + k < n) {
                    const float4* xr = (const float4*)(x + (size_t)(base + k) * DIN);
                    float4 v = xr[lane];
                    acc[k] = v.x * wv.x + v.y * wv.y + v.z * wv.z + v.w * wv.w;
                } else acc[k] = 0.f;
            }
        }
        #pragma unroll
        for (int o = 16; o; o >>= 1) {
            acc[0] += __shfl_xor_sync(0xFFFFFFFFu, acc[0], o);
            acc[1] += __shfl_xor_sync(0xFFFFFFFFu, acc[1], o);
            acc[2] += __shfl_xor_sync(0xFFFFFFFFu, acc[2], o);
            acc[3] += __shfl_xor_sync(0xFFFFFFFFu, acc[3], o);
        }
        if (lane < 4 && base + lane < n)
            g_s[base + lane] = acc[lane];
    } else {
        int e4 = ((blockIdx.x - nodeBlocks) * blockDim.x + threadIdx.x) * 4;
        if (e4 + 3 < E) {
            int4   d = ldcs4i(dst + e4);
            float4 w = ldcs4f(ew + e4);
            atomicAdd(&g_deg[d.x], w.x);
            atomicAdd(&g_deg[d.y], w.y);
            atomicAdd(&g_deg[d.z], w.z);
            atomicAdd(&g_deg[d.w], w.w);
        } else {
            for (int e = e4; e < E; ++e)
                atomicAdd(&g_deg[dst[e]], ew[e]);
        }
    }
}

// ---------------------------------------------------------------------------
// K2: dis = rsqrt(1+deg); p1 = dis*s; H = {dis, p1}.  float4 over 4 nodes.
// Block 0 additionally computes c1 = b1.(W2@fc_w), c2 = b2.fc_w + fc_b.
// ---------------------------------------------------------------------------
__global__ void k_nodeB(int n,
                        const float* __restrict__ b1, const float* __restrict__ W2,
                        const float* __restrict__ b2,
                        const float* __restrict__ fc_w, const float* __restrict__ fc_b) {
    if (blockIdx.x == 0) {
        __shared__ float su[HDIM];
        int t = threadIdx.x;
        if (t < HDIM) {
            float a = 0.f;
            #pragma unroll 8
            for (int j = 0; j < HDIM; ++j) a += W2[t * HDIM + j] * fc_w[j];
            su[t] = a;
        }
        __syncthreads();
        if (t == 0) {
            float c1 = 0.f, c2 = 0.f;
            for (int j = 0; j < HDIM; ++j) { c1 += b1[j] * su[j]; c2 += b2[j] * fc_w[j]; }
            g_c1 = c1;
            g_c2 = c2 + fc_b[0];
        }
    }

    int i = blockIdx.x * blockDim.x + threadIdx.x;
    int nvec = n >> 2;
    if (i < nvec) {
        float4 dg = ((const float4*)g_deg)[i];
        float4 s  = ((const float4*)g_s)[i];
        float4 ds;
        ds.x = rsqrtf(dg.x + 1.f); ds.y = rsqrtf(dg.y + 1.f);
        ds.z = rsqrtf(dg.z + 1.f); ds.w = rsqrtf(dg.w + 1.f);
        float4 p;
        p.x = ds.x * s.x; p.y = ds.y * s.y; p.z = ds.z * s.z; p.w = ds.w * s.w;
        ((float4*)g_p1)[i] = p;
        float4* H4 = (float4*)g_H;                    // 2 float2 per float4
        H4[2 * i]     = make_float4(ds.x, p.x, ds.y, p.y);
        H4[2 * i + 1] = make_float4(ds.z, p.z, ds.w, p.w);
    } else if (i == nvec) {
        for (int j = nvec * 4; j < n; ++j) {
            float dis = rsqrtf(g_deg[j] + 1.f);
            float p = dis * g_s[j];
            g_p1[j] = p;
            g_H[j]  = make_float2(dis, p);
        }
    }
}

// ---------------------------------------------------------------------------
// K3: prop1  H[d].y += ew * p1[src]    (4 edges/thread)
// ---------------------------------------------------------------------------
__global__ void k_prop1(const int* __restrict__ ei,
                        const float* __restrict__ ew, int E) {
    int e4 = (blockIdx.x * blockDim.x + threadIdx.x) * 4;
    if (e4 + 3 < E) {
        int4   s = ldcs4i(ei + e4);
        int4   d = ldcs4i(ei + (size_t)E + e4);
        float4 w = ldcs4f(ew + e4);
        float p0 = g_p1[s.x], p1 = g_p1[s.y], p2 = g_p1[s.z], p3 = g_p1[s.w];
        atomicAdd(&g_H[d.x].y, w.x * p0);
        atomicAdd(&g_H[d.y].y, w.y * p1);
        atomicAdd(&g_H[d.z].y, w.z * p2);
        atomicAdd(&g_H[d.w].y, w.w * p3);
    } else {
        for (int e = e4; e < E; ++e)
            atomicAdd(&g_H[ei[(size_t)E + e]].y, ew[e] * g_p1[ei[e]]);
    }
}

// ---------------------------------------------------------------------------
// K4: prop2  acc2[d] += ew * p2[src],  p2 = dis*(c1 + dis*acc1) from one
//     8-byte gather of H[src].  (4 edges/thread)
// ---------------------------------------------------------------------------
__global__ void k_prop2(const int* __restrict__ ei,
                        const float* __restrict__ ew, int E) {
    float c1 = g_c1;
    int e4 = (blockIdx.x * blockDim.x + threadIdx.x) * 4;
    if (e4 + 3 < E) {
        int4   s = ldcs4i(ei + e4);
        int4   d = ldcs4i(ei + (size_t)E + e4);
        float4 w = ldcs4f(ew + e4);
        float2 h0 = g_H[s.x], h1 = g_H[s.y], h2 = g_H[s.z], h3 = g_H[s.w];
        float p0 = h0.x * fmaf(h0.x, h0.y, c1);
        float p1 = h1.x * fmaf(h1.x, h1.y, c1);
        float p2 = h2.x * fmaf(h2.x, h2.y, c1);
        float p3 = h3.x * fmaf(h3.x, h3.y, c1);
        atomicAdd(&g_acc2[d.x], w.x * p0);
        atomicAdd(&g_acc2[d.y], w.y * p1);
        atomicAdd(&g_acc2[d.z], w.z * p2);
        atomicAdd(&g_acc2[d.w], w.w * p3);
    } else {
        for (int e = e4; e < E; ++e) {
            float2 h = g_H[ei[e]];
            atomicAdd(&g_acc2[ei[(size_t)E + e]], ew[e] * h.x * fmaf(h.x, h.y, c1));
        }
    }
}

// ---------------------------------------------------------------------------
// K5: out = rint(clip(c2 + dis*(p2_self + acc2), 0, 10)); re-zero deg/acc2.
// ---------------------------------------------------------------------------
__global__ void k_out(float* __restrict__ out, int n) {
    float c1 = g_c1, c2 = g_c2;
    int i = blockIdx.x * blockDim.x + threadIdx.x;
    int nvec = n >> 2;
    if (i < nvec) {
        const float4* H4 = (const float4*)g_H;
        float4 ha = H4[2 * i];        // {dis0, a0, dis1, a1}
        float4 hb = H4[2 * i + 1];    // {dis2, a2, dis3, a3}
        float4 a2 = ((const float4*)g_acc2)[i];
        float4 o;
        {
            float p = ha.x * fmaf(ha.x, ha.y, c1);
            o.x = rintf(fminf(fmaxf(fmaf(ha.x, p + a2.x, c2), 0.f), 10.f));
        }
        {
            float p = ha.z * fmaf(ha.z, ha.w, c1);
            o.y = rintf(fminf(fmaxf(fmaf(ha.z, p + a2.y, c2), 0.f), 10.f));
        }
        {
            float p = hb.x * fmaf(hb.x, hb.y, c1);
            o.z = rintf(fminf(fmaxf(fmaf(hb.x, p + a2.z, c2), 0.f), 10.f));
        }
        {
            float p = hb.z * fmaf(hb.z, hb.w, c1);
            o.w = rintf(fminf(fmaxf(fmaf(hb.z, p + a2.w, c2), 0.f), 10.f));
        }
        ((float4*)out)[i] = o;
        ((float4*)g_deg)[i]  = make_float4(0.f, 0.f, 0.f, 0.f);
        ((float4*)g_acc2)[i] = make_float4(0.f, 0.f, 0.f, 0.f);
    } else if (i == nvec) {
        for (int j = nvec * 4; j < n; ++j) {
            float2 h = g_H[j];
            float p = h.x * fmaf(h.x, h.y, c1);
            out[j] = rintf(fminf(fmaxf(fmaf(h.x, p + g_acc2[j], c2), 0.f), 10.f));
            g_deg[j] = 0.f;
            g_acc2[j] = 0.f;
        }
    }
}

extern "C" void kernel_launch(void* const* d_in, const int* in_sizes, int n_in,
                              void* d_out, int out_size) {
    const float* x    = (const float*)d_in[0];
    const int*   ei   = (const int*)d_in[1];    // int32 [2, E]
    const float* ew   = (const float*)d_in[2];
    const float* W1   = (const float*)d_in[3];
    const float* b1   = (const float*)d_in[4];
    const float* W2   = (const float*)d_in[5];
    const float* b2   = (const float*)d_in[6];
    const float* fc_w = (const float*)d_in[7];
    const float* fc_b = (const float*)d_in[8];
    float*       out  = (float*)d_out;

    const int E = in_sizes[2];             // 1600000
    const int N = in_sizes[0] / DIN;       // 100000

    const int TB = 256;
    const int nb_edges4 = ((E + 3) / 4 + TB - 1) / TB;                  // 1563
    const int nodeBlocks = (((N + 3) / 4) + (TB / 32) - 1) / (TB / 32); // 3125
    const int nb_vec = ((N >> 2) + 1 + TB - 1) / TB;

    k_fused<<<nodeBlocks + nb_edges4, TB>>>(x, N, nodeBlocks, ei + E, ew, E,
                                            W1, W2, fc_w);
    k_nodeB<<<nb_vec, TB>>>(N, b1, W2, b2, fc_w, fc_b);
    k_prop1<<<nb_edges4, TB>>>(ei, ew, E);
    k_prop2<<<nb_edges4, TB>>>(ei, ew, E);
    k_out<<<nb_vec, TB>>>(out, N);
}

// round 9
// speedup vs baseline: 2.9264x; 2.9264x over previous
#include <cuda_runtime.h>

#define N_NODES 100000
#define DIN     128
#define HDIM    64

// Scratch (device globals; zeroed at module load; k_out re-zeroes g_deg/g_acc2)
__device__ float  g_deg[N_NODES];     // edge-only degree (self-loop +1 at use)
__device__ float  g_s[N_NODES];       // raw dot product x.w
__device__ float  g_p1[N_NODES];      // dis * s (layer-1 gather array)
__device__ float2 g_H[N_NODES];       // {dis, acc1}; acc1 init = dis*s (self-loop)
__device__ float  g_acc2[N_NODES];    // layer-2 edge accumulator (zeroed)
__device__ __align__(16) float g_w[DIN];
__device__ float  g_c1;
__device__ float  g_c2;

__device__ __forceinline__ int4   ldcs4i(const int* p)   { return __ldcs((const int4*)p); }
__device__ __forceinline__ float4 ldcs4f(const float* p) { return __ldcs((const float4*)p); }

// ---------------------------------------------------------------------------
// K0: weight collapse ONCE (1 block, 128 threads).
//   u = W2 @ fc_w (64), w = W1 @ u (128), c1 = b1.u, c2 = b2.fc_w + fc_b
// ---------------------------------------------------------------------------
__global__ void k_init(const float* __restrict__ W1, const float* __restrict__ b1,
                       const float* __restrict__ W2, const float* __restrict__ b2,
                       const float* __restrict__ fc_w, const float* __restrict__ fc_b) {
    __shared__ float u[HDIM];
    int t = threadIdx.x;
    if (t < HDIM) {
        float a = 0.f;
        #pragma unroll 8
        for (int j = 0; j < HDIM; ++j) a += W2[t * HDIM + j] * fc_w[j];
        u[t] = a;
    }
    __syncthreads();
    if (t < DIN) {
        float a = 0.f;
        #pragma unroll 8
        for (int j = 0; j < HDIM; ++j) a += W1[t * HDIM + j] * u[j];
        g_w[t] = a;
    }
    if (t == 0) {
        float c1 = 0.f, c2 = 0.f;
        for (int j = 0; j < HDIM; ++j) { c1 += b1[j] * u[j]; c2 += b2[j] * fc_w[j]; }
        g_c1 = c1;
        g_c2 = c2 + fc_b[0];
    }
}

// ---------------------------------------------------------------------------
// K1 (fused):
//   blocks [0, nodeBlocks):           s[i] = x[i].w  (4 nodes/warp; g_w staged
//                                     through 512 B of smem -- precomputed)
//   blocks [nodeBlocks, +edgeBlocks): deg[dst] += ew (4 edges/thread)
// ---------------------------------------------------------------------------
__global__ void k_fused(const float* __restrict__ x, int n, int nodeBlocks,
                        const int* __restrict__ dst, const float* __restrict__ ew, int E) {
    if ((int)blockIdx.x < nodeBlocks) {
        __shared__ __align__(16) float sw[DIN];
        int t = threadIdx.x;
        if (t < DIN) sw[t] = g_w[t];
        __syncthreads();

        int warp = blockIdx.x * (blockDim.x >> 5) + (t >> 5);
        int lane = t & 31;
        int base = warp * 4;
        if (base >= n) return;

        float4 wv = ((const float4*)sw)[lane];
        float acc[4];
        if (base + 3 < n) {
            const float4* xr = (const float4*)(x + (size_t)base * DIN);
            float4 v0 = xr[lane];
            float4 v1 = xr[32 + lane];
            float4 v2 = xr[64 + lane];
            float4 v3 = xr[96 + lane];
            acc[0] = v0.x * wv.x + v0.y * wv.y + v0.z * wv.z + v0.w * wv.w;
            acc[1] = v1.x * wv.x + v1.y * wv.y + v1.z * wv.z + v1.w * wv.w;
            acc[2] = v2.x * wv.x + v2.y * wv.y + v2.z * wv.z + v2.w * wv.w;
            acc[3] = v3.x * wv.x + v3.y * wv.y + v3.z * wv.z + v3.w * wv.w;
        } else {
            #pragma unroll
            for (int k = 0; k < 4; ++k) {
                if (base + k < n) {
                    const float4* xr = (const float4*)(x + (size_t)(base + k) * DIN);
                    float4 v = xr[lane];
                    acc[k] = v.x * wv.x + v.y * wv.y + v.z * wv.z + v.w * wv.w;
                } else acc[k] = 0.f;
            }
        }
        #pragma unroll
        for (int o = 16; o; o >>= 1) {
            acc[0] += __shfl_xor_sync(0xFFFFFFFFu, acc[0], o);
            acc[1] += __shfl_xor_sync(0xFFFFFFFFu, acc[1], o);
            acc[2] += __shfl_xor_sync(0xFFFFFFFFu, acc[2], o);
            acc[3] += __shfl_xor_sync(0xFFFFFFFFu, acc[3], o);
        }
        if (lane < 4 && base + lane < n)
            g_s[base + lane] = acc[lane];
    } else {
        int e4 = ((blockIdx.x - nodeBlocks) * blockDim.x + threadIdx.x) * 4;
        if (e4 + 3 < E) {
            int4   d = ldcs4i(dst + e4);
            float4 w = ldcs4f(ew + e4);
            atomicAdd(&g_deg[d.x], w.x);
            atomicAdd(&g_deg[d.y], w.y);
            atomicAdd(&g_deg[d.z], w.z);
            atomicAdd(&g_deg[d.w], w.w);
        } else {
            for (int e = e4; e < E; ++e)
                atomicAdd(&g_deg[dst[e]], ew[e]);
        }
    }
}

// ---------------------------------------------------------------------------
// K2: dis = rsqrt(1+deg); p1 = dis*s; H = {dis, p1}.  float4 over 4 nodes.
// ---------------------------------------------------------------------------
__global__ void k_nodeB(int n) {
    int i = blockIdx.x * blockDim.x + threadIdx.x;
    int nvec = n >> 2;
    if (i < nvec) {
        float4 dg = ((const float4*)g_deg)[i];
        float4 s  = ((const float4*)g_s)[i];
        float4 ds;
        ds.x = rsqrtf(dg.x + 1.f); ds.y = rsqrtf(dg.y + 1.f);
        ds.z = rsqrtf(dg.z + 1.f); ds.w = rsqrtf(dg.w + 1.f);
        float4 p;
        p.x = ds.x * s.x; p.y = ds.y * s.y; p.z = ds.z * s.z; p.w = ds.w * s.w;
        ((float4*)g_p1)[i] = p;
        float4* H4 = (float4*)g_H;                    // 2 float2 per float4
        H4[2 * i]     = make_float4(ds.x, p.x, ds.y, p.y);
        H4[2 * i + 1] = make_float4(ds.z, p.z, ds.w, p.w);
    } else if (i == nvec) {
        for (int j = nvec * 4; j < n; ++j) {
            float dis = rsqrtf(g_deg[j] + 1.f);
            float p = dis * g_s[j];
            g_p1[j] = p;
            g_H[j]  = make_float2(dis, p);
        }
    }
}

// ---------------------------------------------------------------------------
// K3: prop1  H[d].y += ew * p1[src]    (4 edges/thread)
// ---------------------------------------------------------------------------
__global__ void k_prop1(const int* __restrict__ ei,
                        const float* __restrict__ ew, int E) {
    int e4 = (blockIdx.x * blockDim.x + threadIdx.x) * 4;
    if (e4 + 3 < E) {
        int4   s = ldcs4i(ei + e4);
        int4   d = ldcs4i(ei + (size_t)E + e4);
        float4 w = ldcs4f(ew + e4);
        float p0 = g_p1[s.x], p1 = g_p1[s.y], p2 = g_p1[s.z], p3 = g_p1[s.w];
        atomicAdd(&g_H[d.x].y, w.x * p0);
        atomicAdd(&g_H[d.y].y, w.y * p1);
        atomicAdd(&g_H[d.z].y, w.z * p2);
        atomicAdd(&g_H[d.w].y, w.w * p3);
    } else {
        for (int e = e4; e < E; ++e)
            atomicAdd(&g_H[ei[(size_t)E + e]].y, ew[e] * g_p1[ei[e]]);
    }
}

// ---------------------------------------------------------------------------
// K4: prop2  acc2[d] += ew * p2[src],  p2 = dis*(c1 + dis*acc1) from one
//     8-byte gather of H[src].  (4 edges/thread)
// ---------------------------------------------------------------------------
__global__ void k_prop2(const int* __restrict__ ei,
                        const float* __restrict__ ew, int E) {
    float c1 = g_c1;
    int e4 = (blockIdx.x * blockDim.x + threadIdx.x) * 4;
    if (e4 + 3 < E) {
        int4   s = ldcs4i(ei + e4);
        int4   d = ldcs4i(ei + (size_t)E + e4);
        float4 w = ldcs4f(ew + e4);
        float2 h0 = g_H[s.x], h1 = g_H[s.y], h2 = g_H[s.z], h3 = g_H[s.w];
        float p0 = h0.x * fmaf(h0.x, h0.y, c1);
        float p1 = h1.x * fmaf(h1.x, h1.y, c1);
        float p2 = h2.x * fmaf(h2.x, h2.y, c1);
        float p3 = h3.x * fmaf(h3.x, h3.y, c1);
        atomicAdd(&g_acc2[d.x], w.x * p0);
        atomicAdd(&g_acc2[d.y], w.y * p1);
        atomicAdd(&g_acc2[d.z], w.z * p2);
        atomicAdd(&g_acc2[d.w], w.w * p3);
    } else {
        for (int e = e4; e < E; ++e) {
            float2 h = g_H[ei[e]];
            atomicAdd(&g_acc2[ei[(size_t)E + e]], ew[e] * h.x * fmaf(h.x, h.y, c1));
        }
    }
}

// ---------------------------------------------------------------------------
// K5: out = rint(clip(c2 + dis*(p2_self + acc2), 0, 10)); re-zero deg/acc2.
// ---------------------------------------------------------------------------
__global__ void k_out(float* __restrict__ out, int n) {
    float c1 = g_c1, c2 = g_c2;
    int i = blockIdx.x * blockDim.x + threadIdx.x;
    int nvec = n >> 2;
    if (i < nvec) {
        const float4* H4 = (const float4*)g_H;
        float4 ha = H4[2 * i];        // {dis0, a0, dis1, a1}
        float4 hb = H4[2 * i + 1];    // {dis2, a2, dis3, a3}
        float4 a2 = ((const float4*)g_acc2)[i];
        float4 o;
        {
            float p = ha.x * fmaf(ha.x, ha.y, c1);
            o.x = rintf(fminf(fmaxf(fmaf(ha.x, p + a2.x, c2), 0.f), 10.f));
        }
        {
            float p = ha.z * fmaf(ha.z, ha.w, c1);
            o.y = rintf(fminf(fmaxf(fmaf(ha.z, p + a2.y, c2), 0.f), 10.f));
        }
        {
            float p = hb.x * fmaf(hb.x, hb.y, c1);
            o.z = rintf(fminf(fmaxf(fmaf(hb.x, p + a2.z, c2), 0.f), 10.f));
        }
        {
            float p = hb.z * fmaf(hb.z, hb.w, c1);
            o.w = rintf(fminf(fmaxf(fmaf(hb.z, p + a2.w, c2), 0.f), 10.f));
        }
        ((float4*)out)[i] = o;
        ((float4*)g_deg)[i]  = make_float4(0.f, 0.f, 0.f, 0.f);
        ((float4*)g_acc2)[i] = make_float4(0.f, 0.f, 0.f, 0.f);
    } else if (i == nvec) {
        for (int j = nvec * 4; j < n; ++j) {
            float2 h = g_H[j];
            float p = h.x * fmaf(h.x, h.y, c1);
            out[j] = rintf(fminf(fmaxf(fmaf(h.x, p + g_acc2[j], c2), 0.f), 10.f));
            g_deg[j] = 0.f;
            g_acc2[j] = 0.f;
        }
    }
}

extern "C" void kernel_launch(void* const* d_in, const int* in_sizes, int n_in,
                              void* d_out, int out_size) {
    const float* x    = (const float*)d_in[0];
    const int*   ei   = (const int*)d_in[1];    // int32 [2, E]
    const float* ew   = (const float*)d_in[2];
    const float* W1   = (const float*)d_in[3];
    const float* b1   = (const float*)d_in[4];
    const float* W2   = (const float*)d_in[5];
    const float* b2   = (const float*)d_in[6];
    const float* fc_w = (const float*)d_in[7];
    const float* fc_b = (const float*)d_in[8];
    float*       out  = (float*)d_out;

    const int E = in_sizes[2];             // 1600000
    const int N = in_sizes[0] / DIN;       // 100000

    const int TB = 256;
    const int nb_edges4 = ((E + 3) / 4 + TB - 1) / TB;                  // 1563
    const int nodeBlocks = (((N + 3) / 4) + (TB / 32) - 1) / (TB / 32); // 3125
    const int nb_vec = ((N >> 2) + 1 + TB - 1) / TB;

    k_init<<<1, 128>>>(W1, b1, W2, b2, fc_w, fc_b);
    k_fused<<<nodeBlocks + nb_edges4, TB>>>(x, N, nodeBlocks, ei + E, ew, E);
    k_nodeB<<<nb_vec, TB>>>(N);
    k_prop1<<<nb_edges4, TB>>>(ei, ew, E);
    k_prop2<<<nb_edges4, TB>>>(ei, ew, E);
    k_out<<<nb_vec, TB>>>(out, N);
}

// round 10
// speedup vs baseline: 3.2538x; 1.1119x over previous
#include <cuda_runtime.h>

#define N_NODES 100000
#define DIN     128
#define HDIM    64

// Scratch (device globals; zeroed at module load; k_out re-zeroes g_deg/g_acc2)
__device__ float  g_deg[N_NODES];     // edge-only degree (self-loop +1 at use)
__device__ float  g_p1[N_NODES];      // dis * s (layer-1 gather array)
__device__ float2 g_H[N_NODES];       // {dis, acc1}; acc1 init = dis*s (self-loop)
__device__ float  g_acc2[N_NODES];    // layer-2 edge accumulator (zeroed)
__device__ __align__(16) float g_w[DIN];
__device__ float  g_c1;
__device__ float  g_c2;

__device__ __forceinline__ int4   ldcs4i(const int* p)   { return __ldcs((const int4*)p); }
__device__ __forceinline__ float4 ldcs4f(const float* p) { return __ldcs((const float4*)p); }

// ---------------------------------------------------------------------------
// K1 (fused, independent work):
//   block 0:        weight collapse  u = W2@fc_w, w = W1@u, c1 = b1.u,
//                   c2 = b2.fc_w + fc_b
//   blocks 1..E4:   deg[dst] += ew   (4 edges/thread)
// ---------------------------------------------------------------------------
__global__ void k_init_deg(const float* __restrict__ W1, const float* __restrict__ b1,
                           const float* __restrict__ W2, const float* __restrict__ b2,
                           const float* __restrict__ fc_w, const float* __restrict__ fc_b,
                           const int* __restrict__ dst, const float* __restrict__ ew,
                           int E) {
    if (blockIdx.x == 0) {
        __shared__ float u[HDIM];
        int t = threadIdx.x;
        if (t < HDIM) {
            float a = 0.f;
            #pragma unroll 8
            for (int j = 0; j < HDIM; ++j) a += W2[t * HDIM + j] * fc_w[j];
            u[t] = a;
        }
        __syncthreads();
        if (t < DIN) {
            float a = 0.f;
            #pragma unroll 8
            for (int j = 0; j < HDIM; ++j) a += W1[t * HDIM + j] * u[j];
            g_w[t] = a;
        }
        if (t == 0) {
            float c1 = 0.f, c2 = 0.f;
            for (int j = 0; j < HDIM; ++j) { c1 += b1[j] * u[j]; c2 += b2[j] * fc_w[j]; }
            g_c1 = c1;
            g_c2 = c2 + fc_b[0];
        }
        return;
    }
    int e4 = ((blockIdx.x - 1) * blockDim.x + threadIdx.x) * 4;
    if (e4 + 3 < E) {
        int4   d = ldcs4i(dst + e4);
        float4 w = ldcs4f(ew + e4);
        atomicAdd(&g_deg[d.x], w.x);
        atomicAdd(&g_deg[d.y], w.y);
        atomicAdd(&g_deg[d.z], w.z);
        atomicAdd(&g_deg[d.w], w.w);
    } else {
        for (int e = e4; e < E; ++e)
            atomicAdd(&g_deg[dst[e]], ew[e]);
    }
}

// ---------------------------------------------------------------------------
// K2: per node (4 per warp): s = x.w; dis = rsqrt(1+deg); p1 = dis*s;
//     H = {dis, p1}.   Single pass -- no intermediate g_s round-trip.
// ---------------------------------------------------------------------------
__global__ void k_node(const float* __restrict__ x, int n) {
    __shared__ __align__(16) float sw[DIN];
    int t = threadIdx.x;
    if (t < DIN) sw[t] = g_w[t];
    __syncthreads();

    int warp = blockIdx.x * (blockDim.x >> 5) + (t >> 5);
    int lane = t & 31;
    int base = warp * 4;
    if (base >= n) return;

    float4 wv = ((const float4*)sw)[lane];
    float acc[4];
    if (base + 3 < n) {
        const float4* xr = (const float4*)(x + (size_t)base * DIN);
        float4 v0 = xr[lane];
        float4 v1 = xr[32 + lane];
        float4 v2 = xr[64 + lane];
        float4 v3 = xr[96 + lane];
        acc[0] = v0.x * wv.x + v0.y * wv.y + v0.z * wv.z + v0.w * wv.w;
        acc[1] = v1.x * wv.x + v1.y * wv.y + v1.z * wv.z + v1.w * wv.w;
        acc[2] = v2.x * wv.x + v2.y * wv.y + v2.z * wv.z + v2.w * wv.w;
        acc[3] = v3.x * wv.x + v3.y * wv.y + v3.z * wv.z + v3.w * wv.w;
    } else {
        #pragma unroll
        for (int k = 0; k < 4; ++k) {
            if (base + k < n) {
                const float4* xr = (const float4*)(x + (size_t)(base + k) * DIN);
                float4 v = xr[lane];
                acc[k] = v.x * wv.x + v.y * wv.y + v.z * wv.z + v.w * wv.w;
            } else acc[k] = 0.f;
        }
    }
    #pragma unroll
    for (int o = 16; o; o >>= 1) {
        acc[0] += __shfl_xor_sync(0xFFFFFFFFu, acc[0], o);
        acc[1] += __shfl_xor_sync(0xFFFFFFFFu, acc[1], o);
        acc[2] += __shfl_xor_sync(0xFFFFFFFFu, acc[2], o);
        acc[3] += __shfl_xor_sync(0xFFFFFFFFu, acc[3], o);
    }
    if (lane < 4 && base + lane < n) {
        int node = base + lane;
        float dis = rsqrtf(g_deg[node] + 1.f);
        float p = dis * acc[lane];
        g_p1[node] = p;
        g_H[node]  = make_float2(dis, p);
    }
}

// ---------------------------------------------------------------------------
// K3: prop1  H[d].y += ew * p1[src]    (4 edges/thread)
// ---------------------------------------------------------------------------
__global__ void k_prop1(const int* __restrict__ ei,
                        const float* __restrict__ ew, int E) {
    int e4 = (blockIdx.x * blockDim.x + threadIdx.x) * 4;
    if (e4 + 3 < E) {
        int4   s = ldcs4i(ei + e4);
        int4   d = ldcs4i(ei + (size_t)E + e4);
        float4 w = ldcs4f(ew + e4);
        float p0 = g_p1[s.x], p1 = g_p1[s.y], p2 = g_p1[s.z], p3 = g_p1[s.w];
        atomicAdd(&g_H[d.x].y, w.x * p0);
        atomicAdd(&g_H[d.y].y, w.y * p1);
        atomicAdd(&g_H[d.z].y, w.z * p2);
        atomicAdd(&g_H[d.w].y, w.w * p3);
    } else {
        for (int e = e4; e < E; ++e)
            atomicAdd(&g_H[ei[(size_t)E + e]].y, ew[e] * g_p1[ei[e]]);
    }
}

// ---------------------------------------------------------------------------
// K4: prop2  acc2[d] += ew * p2[src],  p2 = dis*(c1 + dis*acc1) from one
//     8-byte gather of H[src].  (4 edges/thread)
// ---------------------------------------------------------------------------
__global__ void k_prop2(const int* __restrict__ ei,
                        const float* __restrict__ ew, int E) {
    float c1 = g_c1;
    int e4 = (blockIdx.x * blockDim.x + threadIdx.x) * 4;
    if (e4 + 3 < E) {
        int4   s = ldcs4i(ei + e4);
        int4   d = ldcs4i(ei + (size_t)E + e4);
        float4 w = ldcs4f(ew + e4);
        float2 h0 = g_H[s.x], h1 = g_H[s.y], h2 = g_H[s.z], h3 = g_H[s.w];
        float p0 = h0.x * fmaf(h0.x, h0.y, c1);
        float p1 = h1.x * fmaf(h1.x, h1.y, c1);
        float p2 = h2.x * fmaf(h2.x, h2.y, c1);
        float p3 = h3.x * fmaf(h3.x, h3.y, c1);
        atomicAdd(&g_acc2[d.x], w.x * p0);
        atomicAdd(&g_acc2[d.y], w.y * p1);
        atomicAdd(&g_acc2[d.z], w.z * p2);
        atomicAdd(&g_acc2[d.w], w.w * p3);
    } else {
        for (int e = e4; e < E; ++e) {
            float2 h = g_H[ei[e]];
            atomicAdd(&g_acc2[ei[(size_t)E + e]], ew[e] * h.x * fmaf(h.x, h.y, c1));
        }
    }
}

// ---------------------------------------------------------------------------
// K5: out = rint(clip(c2 + dis*(p2_self + acc2), 0, 10)); re-zero deg/acc2.
// ---------------------------------------------------------------------------
__global__ void k_out(float* __restrict__ out, int n) {
    float c1 = g_c1, c2 = g_c2;
    int i = blockIdx.x * blockDim.x + threadIdx.x;
    int nvec = n >> 2;
    if (i < nvec) {
        const float4* H4 = (const float4*)g_H;
        float4 ha = H4[2 * i];        // {dis0, a0, dis1, a1}
        float4 hb = H4[2 * i + 1];    // {dis2, a2, dis3, a3}
        float4 a2 = ((const float4*)g_acc2)[i];
        float4 o;
        {
            float p = ha.x * fmaf(ha.x, ha.y, c1);
            o.x = rintf(fminf(fmaxf(fmaf(ha.x, p + a2.x, c2), 0.f), 10.f));
        }
        {
            float p = ha.z * fmaf(ha.z, ha.w, c1);
            o.y = rintf(fminf(fmaxf(fmaf(ha.z, p + a2.y, c2), 0.f), 10.f));
        }
        {
            float p = hb.x * fmaf(hb.x, hb.y, c1);
            o.z = rintf(fminf(fmaxf(fmaf(hb.x, p + a2.z, c2), 0.f), 10.f));
        }
        {
            float p = hb.z * fmaf(hb.z, hb.w, c1);
            o.w = rintf(fminf(fmaxf(fmaf(hb.z, p + a2.w, c2), 0.f), 10.f));
        }
        ((float4*)out)[i] = o;
        ((float4*)g_deg)[i]  = make_float4(0.f, 0.f, 0.f, 0.f);
        ((float4*)g_acc2)[i] = make_float4(0.f, 0.f, 0.f, 0.f);
    } else if (i == nvec) {
        for (int j = nvec * 4; j < n; ++j) {
            float2 h = g_H[j];
            float p = h.x * fmaf(h.x, h.y, c1);
            out[j] = rintf(fminf(fmaxf(fmaf(h.x, p + g_acc2[j], c2), 0.f), 10.f));
            g_deg[j] = 0.f;
            g_acc2[j] = 0.f;
        }
    }
}

extern "C" void kernel_launch(void* const* d_in, const int* in_sizes, int n_in,
                              void* d_out, int out_size) {
    const float* x    = (const float*)d_in[0];
    const int*   ei   = (const int*)d_in[1];    // int32 [2, E]
    const float* ew   = (const float*)d_in[2];
    const float* W1   = (const float*)d_in[3];
    const float* b1   = (const float*)d_in[4];
    const float* W2   = (const float*)d_in[5];
    const float* b2   = (const float*)d_in[6];
    const float* fc_w = (const float*)d_in[7];
    const float* fc_b = (const float*)d_in[8];
    float*       out  = (float*)d_out;

    const int E = in_sizes[2];             // 1600000
    const int N = in_sizes[0] / DIN;       // 100000

    const int TB = 256;
    const int nb_edges4 = ((E + 3) / 4 + TB - 1) / TB;                  // 1563
    const int nodeBlocks = (((N + 3) / 4) + (TB / 32) - 1) / (TB / 32); // 3125
    const int nb_vec = ((N >> 2) + 1 + TB - 1) / TB;

    k_init_deg<<<1 + nb_edges4, TB>>>(W1, b1, W2, b2, fc_w, fc_b, ei + E, ew, E);
    k_node<<<nodeBlocks, TB>>>(x, N);
    k_prop1<<<nb_edges4, TB>>>(ei, ew, E);
    k_prop2<<<nb_edges4, TB>>>(ei, ew, E);
    k_out<<<nb_vec, TB>>>(out, N);
}

// round 11
// speedup vs baseline: 3.4639x; 1.0646x over previous
#include <cuda_runtime.h>

#define N_NODES 100000
#define DIN     128
#define HDIM    64

// Scratch (device globals; zeroed at module load; k_out re-zeroes g_deg/g_acc2)
__device__ float  g_deg[N_NODES];     // edge-only degree (self-loop +1 at use)
__device__ float  g_p1[N_NODES];      // dis * s (layer-1 gather array)
__device__ float2 g_H[N_NODES];       // {dis, acc1}; acc1 init = dis*s (self-loop)
__device__ float  g_acc2[N_NODES];    // layer-2 edge accumulator (zeroed)
__device__ __align__(16) float g_w[DIN];
__device__ float  g_c1;
__device__ float  g_c2;

// ---------------------------------------------------------------------------
// K1 (fused, independent work):
//   block 0:        weight collapse  u = W2@fc_w, w = W1@u, c1 = b1.u,
//                   c2 = b2.fc_w + fc_b
//   blocks 1..E4:   deg[dst] += ew   (4 edges/thread)
// ---------------------------------------------------------------------------
__global__ void k_init_deg(const float* __restrict__ W1, const float* __restrict__ b1,
                           const float* __restrict__ W2, const float* __restrict__ b2,
                           const float* __restrict__ fc_w, const float* __restrict__ fc_b,
                           const int* __restrict__ dst, const float* __restrict__ ew,
                           int E) {
    if (blockIdx.x == 0) {
        __shared__ float u[HDIM];
        int t = threadIdx.x;
        if (t < HDIM) {
            float a = 0.f;
            #pragma unroll 8
            for (int j = 0; j < HDIM; ++j) a += W2[t * HDIM + j] * fc_w[j];
            u[t] = a;
        }
        __syncthreads();
        if (t < DIN) {
            float a = 0.f;
            #pragma unroll 8
            for (int j = 0; j < HDIM; ++j) a += W1[t * HDIM + j] * u[j];
            g_w[t] = a;
        }
        if (t == 0) {
            float c1 = 0.f, c2 = 0.f;
            for (int j = 0; j < HDIM; ++j) { c1 += b1[j] * u[j]; c2 += b2[j] * fc_w[j]; }
            g_c1 = c1;
            g_c2 = c2 + fc_b[0];
        }
        return;
    }
    int e4 = ((blockIdx.x - 1) * blockDim.x + threadIdx.x) * 4;
    if (e4 + 3 < E) {
        int4   d = *(const int4*)(dst + e4);
        float4 w = *(const float4*)(ew + e4);
        atomicAdd(&g_deg[d.x], w.x);
        atomicAdd(&g_deg[d.y], w.y);
        atomicAdd(&g_deg[d.z], w.z);
        atomicAdd(&g_deg[d.w], w.w);
    } else {
        for (int e = e4; e < E; ++e)
            atomicAdd(&g_deg[dst[e]], ew[e]);
    }
}

// ---------------------------------------------------------------------------
// K2 (PDL secondary): prefetch x rows BEFORE grid-dependency sync, then
//   dis = rsqrt(1+deg); p1 = dis*(x.w); H = {dis, p1}.
// ---------------------------------------------------------------------------
__global__ void k_node(const float* __restrict__ x, int n) {
    int t = threadIdx.x;
    int warp = blockIdx.x * (blockDim.x >> 5) + (t >> 5);
    int lane = t & 31;
    int base = warp * 4;

    // Prefetch x (input array — independent of init_deg's writes)
    float4 v[4];
    bool full = (base + 3 < n);
    if (full) {
        const float4* xr = (const float4*)(x + (size_t)base * DIN);
        v[0] = xr[lane];
        v[1] = xr[32 + lane];
        v[2] = xr[64 + lane];
        v[3] = xr[96 + lane];
    }

    cudaGridDependencySynchronize();   // wait for init_deg (g_w, g_deg)

    __shared__ __align__(16) float sw[DIN];
    if (t < DIN) sw[t] = g_w[t];
    __syncthreads();
    if (base >= n) return;

    float4 wv = ((const float4*)sw)[lane];
    float acc[4];
    if (full) {
        #pragma unroll
        for (int k = 0; k < 4; ++k)
            acc[k] = v[k].x * wv.x + v[k].y * wv.y + v[k].z * wv.z + v[k].w * wv.w;
    } else {
        #pragma unroll
        for (int k = 0; k < 4; ++k) {
            if (base + k < n) {
                const float4* xr = (const float4*)(x + (size_t)(base + k) * DIN);
                float4 vv = xr[lane];
                acc[k] = vv.x * wv.x + vv.y * wv.y + vv.z * wv.z + vv.w * wv.w;
            } else acc[k] = 0.f;
        }
    }
    #pragma unroll
    for (int o = 16; o; o >>= 1) {
        acc[0] += __shfl_xor_sync(0xFFFFFFFFu, acc[0], o);
        acc[1] += __shfl_xor_sync(0xFFFFFFFFu, acc[1], o);
        acc[2] += __shfl_xor_sync(0xFFFFFFFFu, acc[2], o);
        acc[3] += __shfl_xor_sync(0xFFFFFFFFu, acc[3], o);
    }
    if (lane < 4 && base + lane < n) {
        int node = base + lane;
        float dis = rsqrtf(g_deg[node] + 1.f);
        float p = dis * acc[lane];
        g_p1[node] = p;
        g_H[node]  = make_float2(dis, p);
    }
}

// ---------------------------------------------------------------------------
// K3 (PDL secondary): prop1  H[d].y += ew * p1[src]
// ---------------------------------------------------------------------------
__global__ void k_prop1(const int* __restrict__ ei,
                        const float* __restrict__ ew, int E) {
    int e4 = (blockIdx.x * blockDim.x + threadIdx.x) * 4;
    int4 s, d; float4 w;
    bool full = (e4 + 3 < E);
    if (full) {
        s = *(const int4*)(ei + e4);
        d = *(const int4*)(ei + (size_t)E + e4);
        w = *(const float4*)(ew + e4);
    }
    cudaGridDependencySynchronize();   // wait for k_node (g_p1, g_H)
    if (full) {
        float p0 = g_p1[s.x], p1 = g_p1[s.y], p2 = g_p1[s.z], p3 = g_p1[s.w];
        atomicAdd(&g_H[d.x].y, w.x * p0);
        atomicAdd(&g_H[d.y].y, w.y * p1);
        atomicAdd(&g_H[d.z].y, w.z * p2);
        atomicAdd(&g_H[d.w].y, w.w * p3);
    } else {
        for (int e = e4; e < E; ++e)
            atomicAdd(&g_H[ei[(size_t)E + e]].y, ew[e] * g_p1[ei[e]]);
    }
}

// ---------------------------------------------------------------------------
// K4 (PDL secondary): prop2  acc2[d] += ew * p2[src],
//   p2 = dis*(c1 + dis*acc1) from one 8-byte gather of H[src].
// ---------------------------------------------------------------------------
__global__ void k_prop2(const int* __restrict__ ei,
                        const float* __restrict__ ew, int E) {
    int e4 = (blockIdx.x * blockDim.x + threadIdx.x) * 4;
    int4 s, d; float4 w;
    bool full = (e4 + 3 < E);
    if (full) {
        s = *(const int4*)(ei + e4);
        d = *(const int4*)(ei + (size_t)E + e4);
        w = *(const float4*)(ew + e4);
    }
    cudaGridDependencySynchronize();   // wait for prop1 (g_H complete)
    float c1 = g_c1;
    if (full) {
        float2 h0 = g_H[s.x], h1 = g_H[s.y], h2 = g_H[s.z], h3 = g_H[s.w];
        float p0 = h0.x * fmaf(h0.x, h0.y, c1);
        float p1 = h1.x * fmaf(h1.x, h1.y, c1);
        float p2 = h2.x * fmaf(h2.x, h2.y, c1);
        float p3 = h3.x * fmaf(h3.x, h3.y, c1);
        atomicAdd(&g_acc2[d.x], w.x * p0);
        atomicAdd(&g_acc2[d.y], w.y * p1);
        atomicAdd(&g_acc2[d.z], w.z * p2);
        atomicAdd(&g_acc2[d.w], w.w * p3);
    } else {
        for (int e = e4; e < E; ++e) {
            float2 h = g_H[ei[e]];
            atomicAdd(&g_acc2[ei[(size_t)E + e]], ew[e] * h.x * fmaf(h.x, h.y, c1));
        }
    }
}

// ---------------------------------------------------------------------------
// K5: out = rint(clip(c2 + dis*(p2_self + acc2), 0, 10)); re-zero deg/acc2.
// ---------------------------------------------------------------------------
__global__ void k_out(float* __restrict__ out, int n) {
    float c1 = g_c1, c2 = g_c2;
    int i = blockIdx.x * blockDim.x + threadIdx.x;
    int nvec = n >> 2;
    if (i < nvec) {
        const float4* H4 = (const float4*)g_H;
        float4 ha = H4[2 * i];        // {dis0, a0, dis1, a1}
        float4 hb = H4[2 * i + 1];    // {dis2, a2, dis3, a3}
        float4 a2 = ((const float4*)g_acc2)[i];
        float4 o;
        { float p = ha.x * fmaf(ha.x, ha.y, c1);
          o.x = rintf(fminf(fmaxf(fmaf(ha.x, p + a2.x, c2), 0.f), 10.f)); }
        { float p = ha.z * fmaf(ha.z, ha.w, c1);
          o.y = rintf(fminf(fmaxf(fmaf(ha.z, p + a2.y, c2), 0.f), 10.f)); }
        { float p = hb.x * fmaf(hb.x, hb.y, c1);
          o.z = rintf(fminf(fmaxf(fmaf(hb.x, p + a2.z, c2), 0.f), 10.f)); }
        { float p = hb.z * fmaf(hb.z, hb.w, c1);
          o.w = rintf(fminf(fmaxf(fmaf(hb.z, p + a2.w, c2), 0.f), 10.f)); }
        ((float4*)out)[i] = o;
        ((float4*)g_deg)[i]  = make_float4(0.f, 0.f, 0.f, 0.f);
        ((float4*)g_acc2)[i] = make_float4(0.f, 0.f, 0.f, 0.f);
    } else if (i == nvec) {
        for (int j = nvec * 4; j < n; ++j) {
            float2 h = g_H[j];
            float p = h.x * fmaf(h.x, h.y, c1);
            out[j] = rintf(fminf(fmaxf(fmaf(h.x, p + g_acc2[j], c2), 0.f), 10.f));
            g_deg[j] = 0.f;
            g_acc2[j] = 0.f;
        }
    }
}

// ---------------------------------------------------------------------------
// PDL launch helper
// ---------------------------------------------------------------------------
template <typename... Args>
static void launch_pdl(void (*kern)(Args...), int grid, int block, Args... args) {
    cudaLaunchConfig_t cfg = {};
    cfg.gridDim  = dim3((unsigned)grid, 1, 1);
    cfg.blockDim = dim3((unsigned)block, 1, 1);
    cudaLaunchAttribute attr[1];
    attr[0].id = cudaLaunchAttributeProgrammaticStreamSerialization;
    attr[0].val.programmaticStreamSerializationAllowed = 1;
    cfg.attrs = attr;
    cfg.numAttrs = 1;
    cudaLaunchKernelEx(&cfg, kern, args...);
}

extern "C" void kernel_launch(void* const* d_in, const int* in_sizes, int n_in,
                              void* d_out, int out_size) {
    const float* x    = (const float*)d_in[0];
    const int*   ei   = (const int*)d_in[1];    // int32 [2, E]
    const float* ew   = (const float*)d_in[2];
    const float* W1   = (const float*)d_in[3];
    const float* b1   = (const float*)d_in[4];
    const float* W2   = (const float*)d_in[5];
    const float* b2   = (const float*)d_in[6];
    const float* fc_w = (const float*)d_in[7];
    const float* fc_b = (const float*)d_in[8];
    float*       out  = (float*)d_out;

    const int E = in_sizes[2];             // 1600000
    const int N = in_sizes[0] / DIN;       // 100000

    const int TB = 256;
    const int nb_edges4 = ((E + 3) / 4 + TB - 1) / TB;                  // 1563
    const int nodeBlocks = (((N + 3) / 4) + (TB / 32) - 1) / (TB / 32); // 3125
    const int nb_vec = ((N >> 2) + 1 + TB - 1) / TB;

    k_init_deg<<<1 + nb_edges4, TB>>>(W1, b1, W2, b2, fc_w, fc_b, ei + E, ew, E);
    launch_pdl(k_node, nodeBlocks, TB, x, N);
    launch_pdl(k_prop1, nb_edges4, TB, ei, ew, E);
    launch_pdl(k_prop2, nb_edges4, TB, ei, ew, E);
    k_out<<<nb_vec, TB>>>(out, N);
}

// round 12
// speedup vs baseline: 3.4824x; 1.0054x over previous
#include <cuda_runtime.h>

#define N_NODES 100000
#define DIN     128
#define HDIM    64

// Scratch (device globals; zeroed at module load; k_out re-zeroes g_deg/g_acc2)
__device__ float  g_deg[N_NODES];     // edge-only degree (self-loop +1 at use)
__device__ float  g_p1[N_NODES];      // dis * s (layer-1 gather array)
__device__ float2 g_H[N_NODES];       // {dis, acc1}; acc1 init = dis*s (self-loop)
__device__ float  g_acc2[N_NODES];    // layer-2 edge accumulator (zeroed)
__device__ __align__(16) float g_w[DIN];
__device__ float  g_c1;
__device__ float  g_c2;

// ---------------------------------------------------------------------------
// K1 (fused, independent work):
//   block 0:        weight collapse  u = W2@fc_w, w = W1@u, c1 = b1.u,
//                   c2 = b2.fc_w + fc_b
//   blocks 1..E4:   deg[dst] += ew  (4 edges/thread)  + L2-prefetch of src row
// ---------------------------------------------------------------------------
__global__ void k_init_deg(const float* __restrict__ W1, const float* __restrict__ b1,
                           const float* __restrict__ W2, const float* __restrict__ b2,
                           const float* __restrict__ fc_w, const float* __restrict__ fc_b,
                           const int* __restrict__ src, const int* __restrict__ dst,
                           const float* __restrict__ ew, int E) {
    if (blockIdx.x == 0) {
        __shared__ float u[HDIM];
        int t = threadIdx.x;
        if (t < HDIM) {
            float a = 0.f;
            #pragma unroll 8
            for (int j = 0; j < HDIM; ++j) a += W2[t * HDIM + j] * fc_w[j];
            u[t] = a;
        }
        __syncthreads();
        if (t < DIN) {
            float a = 0.f;
            #pragma unroll 8
            for (int j = 0; j < HDIM; ++j) a += W1[t * HDIM + j] * u[j];
            g_w[t] = a;
        }
        if (t == 0) {
            float c1 = 0.f, c2 = 0.f;
            for (int j = 0; j < HDIM; ++j) { c1 += b1[j] * u[j]; c2 += b2[j] * fc_w[j]; }
            g_c1 = c1;
            g_c2 = c2 + fc_b[0];
        }
        return;
    }
    int e4 = ((blockIdx.x - 1) * blockDim.x + threadIdx.x) * 4;
    // warm L2 with the src row (one prefetch per 128B line) for prop1
    if ((threadIdx.x & 7) == 0 && e4 < E)
        asm volatile("prefetch.global.L2 [%0];" :: "l"(src + e4));
    if (e4 + 3 < E) {
        int4   d = *(const int4*)(dst + e4);
        float4 w = *(const float4*)(ew + e4);
        atomicAdd(&g_deg[d.x], w.x);
        atomicAdd(&g_deg[d.y], w.y);
        atomicAdd(&g_deg[d.z], w.z);
        atomicAdd(&g_deg[d.w], w.w);
    } else {
        for (int e = e4; e < E; ++e)
            atomicAdd(&g_deg[dst[e]], ew[e]);
    }
}

// ---------------------------------------------------------------------------
// K2 (PDL secondary): prefetch x rows (evict-first, keep edge data in L2)
// BEFORE grid-dependency sync, then dis = rsqrt(1+deg); p1 = dis*(x.w);
// H = {dis, p1}.
// ---------------------------------------------------------------------------
__global__ void k_node(const float* __restrict__ x, int n) {
    int t = threadIdx.x;
    int warp = blockIdx.x * (blockDim.x >> 5) + (t >> 5);
    int lane = t & 31;
    int base = warp * 4;

    // Prefetch x (input array — independent of init_deg's writes).
    // __ldcs: streaming / evict-first so the 51 MB x stream does not evict
    // the 32 MB edge working set that prop1/prop2 re-read from L2.
    float4 v[4];
    bool full = (base + 3 < n);
    if (full) {
        const float4* xr = (const float4*)(x + (size_t)base * DIN);
        v[0] = __ldcs(xr + lane);
        v[1] = __ldcs(xr + 32 + lane);
        v[2] = __ldcs(xr + 64 + lane);
        v[3] = __ldcs(xr + 96 + lane);
    }

    cudaGridDependencySynchronize();   // wait for init_deg (g_w, g_deg)

    __shared__ __align__(16) float sw[DIN];
    if (t < DIN) sw[t] = g_w[t];
    __syncthreads();
    if (base >= n) return;

    float4 wv = ((const float4*)sw)[lane];
    float acc[4];
    if (full) {
        #pragma unroll
        for (int k = 0; k < 4; ++k)
            acc[k] = v[k].x * wv.x + v[k].y * wv.y + v[k].z * wv.z + v[k].w * wv.w;
    } else {
        #pragma unroll
        for (int k = 0; k < 4; ++k) {
            if (base + k < n) {
                const float4* xr = (const float4*)(x + (size_t)(base + k) * DIN);
                float4 vv = __ldcs(xr + lane);
                acc[k] = vv.x * wv.x + vv.y * wv.y + vv.z * wv.z + vv.w * wv.w;
            } else acc[k] = 0.f;
        }
    }
    #pragma unroll
    for (int o = 16; o; o >>= 1) {
        acc[0] += __shfl_xor_sync(0xFFFFFFFFu, acc[0], o);
        acc[1] += __shfl_xor_sync(0xFFFFFFFFu, acc[1], o);
        acc[2] += __shfl_xor_sync(0xFFFFFFFFu, acc[2], o);
        acc[3] += __shfl_xor_sync(0xFFFFFFFFu, acc[3], o);
    }
    if (lane < 4 && base + lane < n) {
        int node = base + lane;
        float dis = rsqrtf(g_deg[node] + 1.f);
        float p = dis * acc[lane];
        g_p1[node] = p;
        g_H[node]  = make_float2(dis, p);
    }
}

// ---------------------------------------------------------------------------
// K3 (PDL secondary): prop1  H[d].y += ew * p1[src]
// ---------------------------------------------------------------------------
__global__ void k_prop1(const int* __restrict__ ei,
                        const float* __restrict__ ew, int E) {
    int e4 = (blockIdx.x * blockDim.x + threadIdx.x) * 4;
    int4 s, d; float4 w;
    bool full = (e4 + 3 < E);
    if (full) {
        s = *(const int4*)(ei + e4);
        d = *(const int4*)(ei + (size_t)E + e4);
        w = *(const float4*)(ew + e4);
    }
    cudaGridDependencySynchronize();   // wait for k_node (g_p1, g_H)
    if (full) {
        float p0 = g_p1[s.x], p1 = g_p1[s.y], p2 = g_p1[s.z], p3 = g_p1[s.w];
        atomicAdd(&g_H[d.x].y, w.x * p0);
        atomicAdd(&g_H[d.y].y, w.y * p1);
        atomicAdd(&g_H[d.z].y, w.z * p2);
        atomicAdd(&g_H[d.w].y, w.w * p3);
    } else {
        for (int e = e4; e < E; ++e)
            atomicAdd(&g_H[ei[(size_t)E + e]].y, ew[e] * g_p1[ei[e]]);
    }
}

// ---------------------------------------------------------------------------
// K4 (PDL secondary): prop2  acc2[d] += ew * p2[src],
//   p2 = dis*(c1 + dis*acc1) from one 8-byte gather of H[src].
// ---------------------------------------------------------------------------
__global__ void k_prop2(const int* __restrict__ ei,
                        const float* __restrict__ ew, int E) {
    int e4 = (blockIdx.x * blockDim.x + threadIdx.x) * 4;
    int4 s, d; float4 w;
    bool full = (e4 + 3 < E);
    if (full) {
        s = *(const int4*)(ei + e4);
        d = *(const int4*)(ei + (size_t)E + e4);
        w = *(const float4*)(ew + e4);
    }
    cudaGridDependencySynchronize();   // wait for prop1 (g_H complete)
    float c1 = g_c1;
    if (full) {
        float2 h0 = g_H[s.x], h1 = g_H[s.y], h2 = g_H[s.z], h3 = g_H[s.w];
        float p0 = h0.x * fmaf(h0.x, h0.y, c1);
        float p1 = h1.x * fmaf(h1.x, h1.y, c1);
        float p2 = h2.x * fmaf(h2.x, h2.y, c1);
        float p3 = h3.x * fmaf(h3.x, h3.y, c1);
        atomicAdd(&g_acc2[d.x], w.x * p0);
        atomicAdd(&g_acc2[d.y], w.y * p1);
        atomicAdd(&g_acc2[d.z], w.z * p2);
        atomicAdd(&g_acc2[d.w], w.w * p3);
    } else {
        for (int e = e4; e < E; ++e) {
            float2 h = g_H[ei[e]];
            atomicAdd(&g_acc2[ei[(size_t)E + e]], ew[e] * h.x * fmaf(h.x, h.y, c1));
        }
    }
}

// ---------------------------------------------------------------------------
// K5: out = rint(clip(c2 + dis*(p2_self + acc2), 0, 10)); re-zero deg/acc2.
// ---------------------------------------------------------------------------
__global__ void k_out(float* __restrict__ out, int n) {
    float c1 = g_c1, c2 = g_c2;
    int i = blockIdx.x * blockDim.x + threadIdx.x;
    int nvec = n >> 2;
    if (i < nvec) {
        const float4* H4 = (const float4*)g_H;
        float4 ha = H4[2 * i];        // {dis0, a0, dis1, a1}
        float4 hb = H4[2 * i + 1];    // {dis2, a2, dis3, a3}
        float4 a2 = ((const float4*)g_acc2)[i];
        float4 o;
        { float p = ha.x * fmaf(ha.x, ha.y, c1);
          o.x = rintf(fminf(fmaxf(fmaf(ha.x, p + a2.x, c2), 0.f), 10.f)); }
        { float p = ha.z * fmaf(ha.z, ha.w, c1);
          o.y = rintf(fminf(fmaxf(fmaf(ha.z, p + a2.y, c2), 0.f), 10.f)); }
        { float p = hb.x * fmaf(hb.x, hb.y, c1);
          o.z = rintf(fminf(fmaxf(fmaf(hb.x, p + a2.z, c2), 0.f), 10.f)); }
        { float p = hb.z * fmaf(hb.z, hb.w, c1);
          o.w = rintf(fminf(fmaxf(fmaf(hb.z, p + a2.w, c2), 0.f), 10.f)); }
        ((float4*)out)[i] = o;
        ((float4*)g_deg)[i]  = make_float4(0.f, 0.f, 0.f, 0.f);
        ((float4*)g_acc2)[i] = make_float4(0.f, 0.f, 0.f, 0.f);
    } else if (i == nvec) {
        for (int j = nvec * 4; j < n; ++j) {
            float2 h = g_H[j];
            float p = h.x * fmaf(h.x, h.y, c1);
            out[j] = rintf(fminf(fmaxf(fmaf(h.x, p + g_acc2[j], c2), 0.f), 10.f));
            g_deg[j] = 0.f;
            g_acc2[j] = 0.f;
        }
    }
}

// ---------------------------------------------------------------------------
// PDL launch helper
// ---------------------------------------------------------------------------
template <typename... Args>
static void launch_pdl(void (*kern)(Args...), int grid, int block, Args... args) {
    cudaLaunchConfig_t cfg = {};
    cfg.gridDim  = dim3((unsigned)grid, 1, 1);
    cfg.blockDim = dim3((unsigned)block, 1, 1);
    cudaLaunchAttribute attr[1];
    attr[0].id = cudaLaunchAttributeProgrammaticStreamSerialization;
    attr[0].val.programmaticStreamSerializationAllowed = 1;
    cfg.attrs = attr;
    cfg.numAttrs = 1;
    cudaLaunchKernelEx(&cfg, kern, args...);
}

extern "C" void kernel_launch(void* const* d_in, const int* in_sizes, int n_in,
                              void* d_out, int out_size) {
    const float* x    = (const float*)d_in[0];
    const int*   ei   = (const int*)d_in[1];    // int32 [2, E]
    const float* ew   = (const float*)d_in[2];
    const float* W1   = (const float*)d_in[3];
    const float* b1   = (const float*)d_in[4];
    const float* W2   = (const float*)d_in[5];
    const float* b2   = (const float*)d_in[6];
    const float* fc_w = (const float*)d_in[7];
    const float* fc_b = (const float*)d_in[8];
    float*       out  = (float*)d_out;

    const int E = in_sizes[2];             // 1600000
    const int N = in_sizes[0] / DIN;       // 100000

    const int TB = 256;
    const int nb_edges4 = ((E + 3) / 4 + TB - 1) / TB;                  // 1563
    const int nodeBlocks = (((N + 3) / 4) + (TB / 32) - 1) / (TB / 32); // 3125
    const int nb_vec = ((N >> 2) + 1 + TB - 1) / TB;

    k_init_deg<<<1 + nb_edges4, TB>>>(W1, b1, W2, b2, fc_w, fc_b, ei, ei + E, ew, E);
    launch_pdl(k_node, nodeBlocks, TB, x, N);
    launch_pdl(k_prop1, nb_edges4, TB, ei, ew, E);
    launch_pdl(k_prop2, nb_edges4, TB, ei, ew, E);
    k_out<<<nb_vec, TB>>>(out, N);
}

// round 13
// speedup vs baseline: 3.6204x; 1.0396x over previous
#include <cuda_runtime.h>

#define N_NODES 100000
#define DIN     128
#define HDIM    64

// Scratch (device globals; zeroed at module load; k_out re-zeroes g_deg/g_acc2)
__device__ float  g_deg[N_NODES];     // edge-only degree (self-loop +1 at use)
__device__ float  g_p1[N_NODES];      // dis * s (layer-1 gather array)
__device__ float2 g_H[N_NODES];       // {dis, acc1}; acc1 init = dis*s (self-loop)
__device__ float  g_acc2[N_NODES];    // layer-2 edge accumulator (zeroed)
__device__ __align__(16) float g_w[DIN];
__device__ float  g_c1;
__device__ float  g_c2;

// ---------------------------------------------------------------------------
// K1 (fused, independent work):
//   block 0:        weight collapse  u = W2@fc_w, w = W1@u, c1 = b1.u,
//                   c2 = b2.fc_w + fc_b
//   blocks 1..E4:   deg[dst] += ew  (4 edges/thread)  + L2-prefetch of src row
// ---------------------------------------------------------------------------
__global__ void k_init_deg(const float* __restrict__ W1, const float* __restrict__ b1,
                           const float* __restrict__ W2, const float* __restrict__ b2,
                           const float* __restrict__ fc_w, const float* __restrict__ fc_b,
                           const int* __restrict__ src, const int* __restrict__ dst,
                           const float* __restrict__ ew, int E) {
    if (blockIdx.x == 0) {
        __shared__ float u[HDIM];
        int t = threadIdx.x;
        if (t < HDIM) {
            float a = 0.f;
            #pragma unroll 8
            for (int j = 0; j < HDIM; ++j) a += W2[t * HDIM + j] * fc_w[j];
            u[t] = a;
        }
        __syncthreads();
        if (t < DIN) {
            float a = 0.f;
            #pragma unroll 8
            for (int j = 0; j < HDIM; ++j) a += W1[t * HDIM + j] * u[j];
            g_w[t] = a;
        }
        if (t == 0) {
            float c1 = 0.f, c2 = 0.f;
            for (int j = 0; j < HDIM; ++j) { c1 += b1[j] * u[j]; c2 += b2[j] * fc_w[j]; }
            g_c1 = c1;
            g_c2 = c2 + fc_b[0];
        }
        return;
    }
    int e4 = ((blockIdx.x - 1) * blockDim.x + threadIdx.x) * 4;
    // warm L2 with the src row (one prefetch per 128B line) for prop1
    if ((threadIdx.x & 7) == 0 && e4 < E)
        asm volatile("prefetch.global.L2 [%0];" :: "l"(src + e4));
    if (e4 + 3 < E) {
        int4   d = *(const int4*)(dst + e4);
        float4 w = *(const float4*)(ew + e4);
        atomicAdd(&g_deg[d.x], w.x);
        atomicAdd(&g_deg[d.y], w.y);
        atomicAdd(&g_deg[d.z], w.z);
        atomicAdd(&g_deg[d.w], w.w);
    } else {
        for (int e = e4; e < E; ++e)
            atomicAdd(&g_deg[dst[e]], ew[e]);
    }
}

// ---------------------------------------------------------------------------
// K2 (PDL secondary): prefetch x rows (evict-first) BEFORE grid-dependency
// sync, then dis = rsqrt(1+deg); p1 = dis*(x.w); H = {dis, p1}.
// g_w read directly per-lane (L1 broadcast) — no smem staging / extra BAR.
// ---------------------------------------------------------------------------
__global__ void k_node(const float* __restrict__ x, int n) {
    int t = threadIdx.x;
    int warp = blockIdx.x * (blockDim.x >> 5) + (t >> 5);
    int lane = t & 31;
    int base = warp * 4;

    // Prefetch x (input array — independent of init_deg's writes).
    float4 v[4];
    bool full = (base + 3 < n);
    if (full) {
        const float4* xr = (const float4*)(x + (size_t)base * DIN);
        v[0] = __ldcs(xr + lane);
        v[1] = __ldcs(xr + 32 + lane);
        v[2] = __ldcs(xr + 64 + lane);
        v[3] = __ldcs(xr + 96 + lane);
    }

    cudaGridDependencySynchronize();   // wait for init_deg (g_w, g_deg)
    if (base >= n) return;

    float4 wv = ((const float4*)g_w)[lane];
    float acc[4];
    if (full) {
        #pragma unroll
        for (int k = 0; k < 4; ++k)
            acc[k] = v[k].x * wv.x + v[k].y * wv.y + v[k].z * wv.z + v[k].w * wv.w;
    } else {
        #pragma unroll
        for (int k = 0; k < 4; ++k) {
            if (base + k < n) {
                const float4* xr = (const float4*)(x + (size_t)(base + k) * DIN);
                float4 vv = __ldcs(xr + lane);
                acc[k] = vv.x * wv.x + vv.y * wv.y + vv.z * wv.z + vv.w * wv.w;
            } else acc[k] = 0.f;
        }
    }
    #pragma unroll
    for (int o = 16; o; o >>= 1) {
        acc[0] += __shfl_xor_sync(0xFFFFFFFFu, acc[0], o);
        acc[1] += __shfl_xor_sync(0xFFFFFFFFu, acc[1], o);
        acc[2] += __shfl_xor_sync(0xFFFFFFFFu, acc[2], o);
        acc[3] += __shfl_xor_sync(0xFFFFFFFFu, acc[3], o);
    }
    if (lane < 4 && base + lane < n) {
        int node = base + lane;
        float dis = rsqrtf(g_deg[node] + 1.f);
        float p = dis * acc[lane];
        g_p1[node] = p;
        g_H[node]  = make_float2(dis, p);
    }
}

// ---------------------------------------------------------------------------
// K3 (PDL secondary): prop1  H[d].y += ew * p1[src]
// ---------------------------------------------------------------------------
__global__ void k_prop1(const int* __restrict__ ei,
                        const float* __restrict__ ew, int E) {
    int e4 = (blockIdx.x * blockDim.x + threadIdx.x) * 4;
    int4 s, d; float4 w;
    bool full = (e4 + 3 < E);
    if (full) {
        s = *(const int4*)(ei + e4);
        d = *(const int4*)(ei + (size_t)E + e4);
        w = *(const float4*)(ew + e4);
    }
    cudaGridDependencySynchronize();   // wait for k_node (g_p1, g_H)
    if (full) {
        float p0 = g_p1[s.x], p1 = g_p1[s.y], p2 = g_p1[s.z], p3 = g_p1[s.w];
        atomicAdd(&g_H[d.x].y, w.x * p0);
        atomicAdd(&g_H[d.y].y, w.y * p1);
        atomicAdd(&g_H[d.z].y, w.z * p2);
        atomicAdd(&g_H[d.w].y, w.w * p3);
    } else {
        for (int e = e4; e < E; ++e)
            atomicAdd(&g_H[ei[(size_t)E + e]].y, ew[e] * g_p1[ei[e]]);
    }
}

// ---------------------------------------------------------------------------
// K4 (PDL secondary): prop2  acc2[d] += ew * p2[src],
//   p2 = dis*(c1 + dis*acc1) from one 8-byte gather of H[src].
// ---------------------------------------------------------------------------
__global__ void k_prop2(const int* __restrict__ ei,
                        const float* __restrict__ ew, int E) {
    int e4 = (blockIdx.x * blockDim.x + threadIdx.x) * 4;
    int4 s, d; float4 w;
    bool full = (e4 + 3 < E);
    if (full) {
        s = *(const int4*)(ei + e4);
        d = *(const int4*)(ei + (size_t)E + e4);
        w = *(const float4*)(ew + e4);
    }
    cudaGridDependencySynchronize();   // wait for prop1 (g_H complete)
    float c1 = g_c1;
    if (full) {
        float2 h0 = g_H[s.x], h1 = g_H[s.y], h2 = g_H[s.z], h3 = g_H[s.w];
        float p0 = h0.x * fmaf(h0.x, h0.y, c1);
        float p1 = h1.x * fmaf(h1.x, h1.y, c1);
        float p2 = h2.x * fmaf(h2.x, h2.y, c1);
        float p3 = h3.x * fmaf(h3.x, h3.y, c1);
        atomicAdd(&g_acc2[d.x], w.x * p0);
        atomicAdd(&g_acc2[d.y], w.y * p1);
        atomicAdd(&g_acc2[d.z], w.z * p2);
        atomicAdd(&g_acc2[d.w], w.w * p3);
    } else {
        for (int e = e4; e < E; ++e) {
            float2 h = g_H[ei[e]];
            atomicAdd(&g_acc2[ei[(size_t)E + e]], ew[e] * h.x * fmaf(h.x, h.y, c1));
        }
    }
}

// ---------------------------------------------------------------------------
// K5 (PDL secondary): out = rint(clip(c2 + dis*(p2_self + acc2), 0, 10));
// re-zero deg/acc2 for graph replay.  H is final after prop1, so it is
// prefetched BEFORE the grid-dependency sync (concurrent with prop2).
// ---------------------------------------------------------------------------
__global__ void k_out(float* __restrict__ out, int n) {
    int i = blockIdx.x * blockDim.x + threadIdx.x;
    int nvec = n >> 2;

    // Pre-sync prefetch of H (written by prop1, which completed before prop2
    // even started; prop2 does not write H).
    float4 ha, hb;
    if (i < nvec) {
        const float4* H4 = (const float4*)g_H;
        ha = H4[2 * i];        // {dis0, a0, dis1, a1}
        hb = H4[2 * i + 1];    // {dis2, a2, dis3, a3}
    }

    cudaGridDependencySynchronize();   // wait for prop2 (g_acc2 complete)
    float c1 = g_c1, c2 = g_c2;

    if (i < nvec) {
        float4 a2 = ((const float4*)g_acc2)[i];
        float4 o;
        { float p = ha.x * fmaf(ha.x, ha.y, c1);
          o.x = rintf(fminf(fmaxf(fmaf(ha.x, p + a2.x, c2), 0.f), 10.f)); }
        { float p = ha.z * fmaf(ha.z, ha.w, c1);
          o.y = rintf(fminf(fmaxf(fmaf(ha.z, p + a2.y, c2), 0.f), 10.f)); }
        { float p = hb.x * fmaf(hb.x, hb.y, c1);
          o.z = rintf(fminf(fmaxf(fmaf(hb.x, p + a2.z, c2), 0.f), 10.f)); }
        { float p = hb.z * fmaf(hb.z, hb.w, c1);
          o.w = rintf(fminf(fmaxf(fmaf(hb.z, p + a2.w, c2), 0.f), 10.f)); }
        ((float4*)out)[i] = o;
        ((float4*)g_deg)[i]  = make_float4(0.f, 0.f, 0.f, 0.f);
        ((float4*)g_acc2)[i] = make_float4(0.f, 0.f, 0.f, 0.f);
    } else if (i == nvec) {
        for (int j = nvec * 4; j < n; ++j) {
            float2 h = g_H[j];
            float p = h.x * fmaf(h.x, h.y, c1);
            out[j] = rintf(fminf(fmaxf(fmaf(h.x, p + g_acc2[j], c2), 0.f), 10.f));
            g_deg[j] = 0.f;
            g_acc2[j] = 0.f;
        }
    }
}

// ---------------------------------------------------------------------------
// PDL launch helper
// ---------------------------------------------------------------------------
template <typename... Args>
static void launch_pdl(void (*kern)(Args...), int grid, int block, Args... args) {
    cudaLaunchConfig_t cfg = {};
    cfg.gridDim  = dim3((unsigned)grid, 1, 1);
    cfg.blockDim = dim3((unsigned)block, 1, 1);
    cudaLaunchAttribute attr[1];
    attr[0].id = cudaLaunchAttributeProgrammaticStreamSerialization;
    attr[0].val.programmaticStreamSerializationAllowed = 1;
    cfg.attrs = attr;
    cfg.numAttrs = 1;
    cudaLaunchKernelEx(&cfg, kern, args...);
}

extern "C" void kernel_launch(void* const* d_in, const int* in_sizes, int n_in,
                              void* d_out, int out_size) {
    const float* x    = (const float*)d_in[0];
    const int*   ei   = (const int*)d_in[1];    // int32 [2, E]
    const float* ew   = (const float*)d_in[2];
    const float* W1   = (const float*)d_in[3];
    const float* b1   = (const float*)d_in[4];
    const float* W2   = (const float*)d_in[5];
    const float* b2   = (const float*)d_in[6];
    const float* fc_w = (const float*)d_in[7];
    const float* fc_b = (const float*)d_in[8];
    float*       out  = (float*)d_out;

    const int E = in_sizes[2];             // 1600000
    const int N = in_sizes[0] / DIN;       // 100000

    const int TB = 256;
    const int nb_edges4 = ((E + 3) / 4 + TB - 1) / TB;                  // 1563
    const int nodeBlocks = (((N + 3) / 4) + (TB / 32) - 1) / (TB / 32); // 3125
    const int nb_vec = ((N >> 2) + 1 + TB - 1) / TB;

    k_init_deg<<<1 + nb_edges4, TB>>>(W1, b1, W2, b2, fc_w, fc_b, ei, ei + E, ew, E);
    launch_pdl(k_node, nodeBlocks, TB, x, N);
    launch_pdl(k_prop1, nb_edges4, TB, ei, ew, E);
    launch_pdl(k_prop2, nb_edges4, TB, ei, ew, E);
    launch_pdl(k_out, nb_vec, TB, out, N);
}